// round 1
// baseline (speedup 1.0000x reference)
#include <cuda_runtime.h>
#include <math.h>

// ---------------- problem constants ----------------
#define BB 4
#define SS 1024
#define DD 512
#define HH 8
#define DH 64
#define LL 6
#define VV 32000
#define MROWS (BB*SS)          // 4096
#define EW (BB*SS*DD)          // 2,097,152 elementwise size

// ---------------- device scratch (allocation-free) ----------------
__device__ float g_h[EW];
__device__ float g_x[EW];
__device__ float g_q[EW];
__device__ float g_k[EW];
__device__ float g_v[EW];
__device__ float g_av[EW];
__device__ float g_t[EW];
__device__ float g_t1[EW];
__device__ float g_t2[EW];
__device__ float g_agg[EW];
__device__ float g_gl[EW];
__device__ float g_sc[(size_t)BB*HH*SS*SS];   // 134 MB attention scores

// ---------------- reductions ----------------
__device__ __forceinline__ float warpSum(float v) {
    #pragma unroll
    for (int o = 16; o > 0; o >>= 1) v += __shfl_xor_sync(0xffffffffu, v, o);
    return v;
}
__device__ __forceinline__ float warpMax(float v) {
    #pragma unroll
    for (int o = 16; o > 0; o >>= 1) v = fmaxf(v, __shfl_xor_sync(0xffffffffu, v, o));
    return v;
}
__device__ __forceinline__ float blockSum(float v) {
    __shared__ float sh[8];
    int lane = threadIdx.x & 31, wid = threadIdx.x >> 5;
    v = warpSum(v);
    if (lane == 0) sh[wid] = v;
    __syncthreads();
    if (wid == 0) {
        float x = (lane < 8) ? sh[lane] : 0.f;
        x = warpSum(x);
        if (lane == 0) sh[0] = x;
    }
    __syncthreads();
    float r = sh[0];
    __syncthreads();
    return r;
}
__device__ __forceinline__ float blockMax(float v) {
    __shared__ float sh[8];
    int lane = threadIdx.x & 31, wid = threadIdx.x >> 5;
    v = warpMax(v);
    if (lane == 0) sh[wid] = v;
    __syncthreads();
    if (wid == 0) {
        float x = (lane < 8) ? sh[lane] : -3.0e38f;
        x = warpMax(x);
        if (lane == 0) sh[0] = x;
    }
    __syncthreads();
    float r = sh[0];
    __syncthreads();
    return r;
}

// ---------------- embedding ----------------
__global__ void embed_kernel(const int* __restrict__ ids,
                             const float* __restrict__ tok,
                             const float* __restrict__ pos) {
    int idx = blockIdx.x * 256 + threadIdx.x;
    int d  = idx & (DD - 1);
    int bs = idx >> 9;             // DD = 512
    int s  = bs & (SS - 1);
    g_h[idx] = tok[(size_t)ids[bs] * DD + d] + pos[(size_t)s * DD + d];
}

// ---------------- layernorm (one block per row, 256 thr, 2 elems/thr) ----------------
__global__ void ln_kernel(const float* __restrict__ in,
                          const float* __restrict__ w,
                          const float* __restrict__ b,
                          float* __restrict__ out) {
    int row = blockIdx.x;
    const float* xp = in + (size_t)row * DD;
    int t = threadIdx.x;
    float v0 = xp[t];
    float v1 = xp[t + 256];
    float s  = blockSum(v0 + v1);
    float s2 = blockSum(v0 * v0 + v1 * v1);
    float mean = s * (1.f / DD);
    float var  = s2 * (1.f / DD) - mean * mean;
    float rstd = rsqrtf(var + 1e-5f);
    float* op = out + (size_t)row * DD;
    op[t]       = (v0 - mean) * rstd * w[t]       + b[t];
    op[t + 256] = (v1 - mean) * rstd * w[t + 256] + b[t + 256];
}

// ---------------- generic GEMM: C = A@B (+bias) (+add) ----------------
// A [M,K] packed, B [K,N] packed, C [M,N] packed. M%128==0, N%64==0, K%16==0.
#define GBM 128
#define GBN 64
#define GBK 16
__global__ void gemm_kernel(const float* __restrict__ A,
                            const float* __restrict__ B,
                            const float* __restrict__ bias,
                            const float* __restrict__ addv,
                            float* __restrict__ C,
                            int M, int N, int K) {
    __shared__ float As[GBK][GBM];
    __shared__ float Bs[GBK][GBN];
    int bm = blockIdx.y * GBM;
    int bn = blockIdx.x * GBN;
    int tid = threadIdx.x;
    int tx = tid & 15;       // N dir, 4 cols each
    int ty = tid >> 4;       // M dir, 8 rows each
    float acc[8][4] = {};
    for (int k0 = 0; k0 < K; k0 += GBK) {
        #pragma unroll
        for (int i = 0; i < 8; i++) {
            int idx = tid + i * 256;
            int r = idx >> 4, c = idx & 15;
            As[c][r] = A[(size_t)(bm + r) * K + k0 + c];
        }
        #pragma unroll
        for (int i = 0; i < 4; i++) {
            int idx = tid + i * 256;
            int r = idx >> 6, c = idx & 63;
            Bs[r][c] = B[(size_t)(k0 + r) * N + bn + c];
        }
        __syncthreads();
        #pragma unroll
        for (int kk = 0; kk < GBK; kk++) {
            float a[8], bv[4];
            #pragma unroll
            for (int i = 0; i < 8; i++) a[i] = As[kk][ty * 8 + i];
            #pragma unroll
            for (int j = 0; j < 4; j++) bv[j] = Bs[kk][tx * 4 + j];
            #pragma unroll
            for (int i = 0; i < 8; i++)
                #pragma unroll
                for (int j = 0; j < 4; j++)
                    acc[i][j] = fmaf(a[i], bv[j], acc[i][j]);
        }
        __syncthreads();
    }
    #pragma unroll
    for (int i = 0; i < 8; i++) {
        size_t r = bm + ty * 8 + i;
        #pragma unroll
        for (int j = 0; j < 4; j++) {
            int c = bn + tx * 4 + j;
            float val = acc[i][j];
            if (bias) val += bias[c];
            if (addv) val += addv[r * N + c];
            C[r * N + c] = val;
        }
    }
}

// ---------------- attention: scores tile (skips masked tiles) ----------------
__global__ void scores_kernel(const float* __restrict__ q,
                              const float* __restrict__ k,
                              float* __restrict__ sc) {
    int tj = blockIdx.x, ti = blockIdx.y;
    if (tj > ti) return;
    int bh = blockIdx.z;
    int b = bh >> 3, h = bh & 7;
    __shared__ float Qs[64][65];
    __shared__ float Ks[64][65];
    int tid = threadIdx.x;
    const float* qb = q + (size_t)(b * SS + ti * 64) * DD + h * DH;
    const float* kb = k + (size_t)(b * SS + tj * 64) * DD + h * DH;
    #pragma unroll
    for (int t = 0; t < 16; t++) {
        int idx = tid + t * 256;
        int r = idx >> 6, d = idx & 63;
        Qs[d][r] = qb[(size_t)r * DD + d];
        Ks[d][r] = kb[(size_t)r * DD + d];
    }
    __syncthreads();
    int tx = tid & 15, ty = tid >> 4;
    float acc[4][4] = {};
    #pragma unroll 16
    for (int d = 0; d < 64; d++) {
        float qa[4], ka[4];
        #pragma unroll
        for (int i = 0; i < 4; i++) qa[i] = Qs[d][ty * 4 + i];
        #pragma unroll
        for (int j = 0; j < 4; j++) ka[j] = Ks[d][tx * 4 + j];
        #pragma unroll
        for (int i = 0; i < 4; i++)
            #pragma unroll
            for (int j = 0; j < 4; j++)
                acc[i][j] = fmaf(qa[i], ka[j], acc[i][j]);
    }
    float* srow = sc + (size_t)bh * SS * SS;
    #pragma unroll
    for (int i = 0; i < 4; i++) {
        int gi = ti * 64 + ty * 4 + i;
        #pragma unroll
        for (int j = 0; j < 4; j++) {
            int gj = tj * 64 + tx * 4 + j;
            float val = acc[i][j] * 0.125f;   // 1/sqrt(64)
            if (gj > gi) val = -1e30f;
            srow[(size_t)gi * SS + gj] = val;
        }
    }
}

// ---------------- softmax over valid prefix (rounded up to tile) ----------------
__global__ void softmax_kernel(float* __restrict__ sc) {
    int row = blockIdx.x;                 // = bh*SS + i
    int i = row & (SS - 1);
    float* p = sc + (size_t)row * SS;
    int n = ((i >> 6) + 1) << 6;          // columns AV will read
    int tid = threadIdx.x;
    float vals[4];
    int cnt = 0;
    for (int j = tid; j < n; j += 256) vals[cnt++] = p[j];
    float m = -1e30f;
    for (int c = 0; c < cnt; c++) m = fmaxf(m, vals[c]);
    m = blockMax(m);
    float e[4], s = 0.f;
    for (int c = 0; c < cnt; c++) { e[c] = expf(vals[c] - m); s += e[c]; }
    s = blockSum(s);
    float inv = 1.f / s;
    cnt = 0;
    for (int j = tid; j < n; j += 256) p[j] = e[cnt++] * inv;
}

// ---------------- AV: attn @ v, K-loop truncated at diagonal ----------------
__global__ void av_kernel(const float* __restrict__ v,
                          const float* __restrict__ sc,
                          float* __restrict__ av) {
    int ti = blockIdx.x;
    int bh = blockIdx.y;
    int b = bh >> 3, h = bh & 7;
    __shared__ float Ps[64][33];
    __shared__ float Vs[32][64];
    const float* srow = sc + (size_t)bh * SS * SS + (size_t)ti * 64 * SS;
    const float* vb = v + (size_t)b * SS * DD + h * DH;
    int tid = threadIdx.x, tx = tid & 15, ty = tid >> 4;
    float acc[4][4] = {};
    int kmax = (ti + 1) * 64;
    for (int k0 = 0; k0 < kmax; k0 += 32) {
        #pragma unroll
        for (int t = 0; t < 8; t++) {
            int idx = tid + t * 256;
            int r = idx >> 5, c = idx & 31;
            Ps[r][c] = srow[(size_t)r * SS + k0 + c];
        }
        #pragma unroll
        for (int t = 0; t < 8; t++) {
            int idx = tid + t * 256;
            int r = idx >> 6, c = idx & 63;
            Vs[r][c] = vb[(size_t)(k0 + r) * DD + c];
        }
        __syncthreads();
        #pragma unroll
        for (int kk = 0; kk < 32; kk++) {
            float a[4], bv[4];
            #pragma unroll
            for (int i = 0; i < 4; i++) a[i] = Ps[ty * 4 + i][kk];
            #pragma unroll
            for (int j = 0; j < 4; j++) bv[j] = Vs[kk][tx * 4 + j];
            #pragma unroll
            for (int i = 0; i < 4; i++)
                #pragma unroll
                for (int j = 0; j < 4; j++)
                    acc[i][j] = fmaf(a[i], bv[j], acc[i][j]);
        }
        __syncthreads();
    }
    float* ob = av + (size_t)(b * SS + ti * 64) * DD + h * DH;
    #pragma unroll
    for (int i = 0; i < 4; i++)
        #pragma unroll
        for (int j = 0; j < 4; j++)
            ob[(size_t)(ty * 4 + i) * DD + tx * 4 + j] = acc[i][j];
}

// ---------------- TreeFFN elementwise ----------------
// agg[b,s] = s==0 ? 0 : relu(t1[b,s-1] + t2[b,s] + bedge)
__global__ void combine_kernel(const float* __restrict__ bedge) {
    int idx = blockIdx.x * 256 + threadIdx.x;
    int d = idx & (DD - 1);
    int s = (idx >> 9) & (SS - 1);
    float r = 0.f;
    if (s != 0) {
        float m = g_t1[idx - DD] + g_t2[idx] + bedge[d];
        r = m > 0.f ? m : 0.f;
    }
    g_agg[idx] = r;
}
// t += sigmoid(gl) * agg
__global__ void gate_kernel() {
    int idx = blockIdx.x * 256 + threadIdx.x;
    float g = 1.f / (1.f + expf(-g_gl[idx]));
    g_t[idx] += g * g_agg[idx];
}
// h += t
__global__ void add_kernel() {
    int idx = blockIdx.x * 256 + threadIdx.x;
    g_h[idx] += g_t[idx];
}

// ---------------- launcher ----------------
extern "C" void kernel_launch(void* const* d_in, const int* in_sizes, int n_in,
                              void* d_out, int out_size) {
    const int*   ids  = (const int*)  d_in[0];
    const float* tok  = (const float*)d_in[1];
    const float* pos  = (const float*)d_in[2];
    const float* Wq   = (const float*)d_in[3];
    const float* bq   = (const float*)d_in[4];
    const float* Wk   = (const float*)d_in[5];
    const float* bk   = (const float*)d_in[6];
    const float* Wv   = (const float*)d_in[7];
    const float* bv   = (const float*)d_in[8];
    const float* Wo   = (const float*)d_in[9];
    const float* bo   = (const float*)d_in[10];
    const float* ln1w = (const float*)d_in[11];
    const float* ln1b = (const float*)d_in[12];
    const float* ln2w = (const float*)d_in[13];
    const float* ln2b = (const float*)d_in[14];
    const float* Win  = (const float*)d_in[15];
    const float* bin_ = (const float*)d_in[16];
    const float* Wed  = (const float*)d_in[17];
    const float* bed  = (const float*)d_in[18];
    const float* Wg   = (const float*)d_in[19];
    const float* bg   = (const float*)d_in[20];
    const float* lnfw = (const float*)d_in[21];
    const float* lnfb = (const float*)d_in[22];
    const float* Whd  = (const float*)d_in[23];
    float* out = (float*)d_out;

    float *h, *x, *q, *k, *v, *av, *t, *t1, *t2, *agg, *gl, *sc;
    cudaGetSymbolAddress((void**)&h,   g_h);
    cudaGetSymbolAddress((void**)&x,   g_x);
    cudaGetSymbolAddress((void**)&q,   g_q);
    cudaGetSymbolAddress((void**)&k,   g_k);
    cudaGetSymbolAddress((void**)&v,   g_v);
    cudaGetSymbolAddress((void**)&av,  g_av);
    cudaGetSymbolAddress((void**)&t,   g_t);
    cudaGetSymbolAddress((void**)&t1,  g_t1);
    cudaGetSymbolAddress((void**)&t2,  g_t2);
    cudaGetSymbolAddress((void**)&agg, g_agg);
    cudaGetSymbolAddress((void**)&gl,  g_gl);
    cudaGetSymbolAddress((void**)&sc,  g_sc);

    const int ewBlocks = EW / 256;         // 8192
    dim3 gD(DD / GBN, MROWS / GBM);        // (8, 32)  N=512 GEMMs
    dim3 gHead(VV / GBN, MROWS / GBM);     // (500, 32)

    embed_kernel<<<ewBlocks, 256>>>(ids, tok, pos);

    for (int l = 0; l < LL; l++) {
        size_t oDD = (size_t)l * DD * DD;
        size_t oD  = (size_t)l * DD;
        size_t o2  = (size_t)l * 2 * DD * DD;

        // --- attention ---
        ln_kernel<<<MROWS, 256>>>(h, ln1w + oD, ln1b + oD, x);
        gemm_kernel<<<gD, 256>>>(x, Wq + oDD, bq + oD, nullptr, q, MROWS, DD, DD);
        gemm_kernel<<<gD, 256>>>(x, Wk + oDD, bk + oD, nullptr, k, MROWS, DD, DD);
        gemm_kernel<<<gD, 256>>>(x, Wv + oDD, bv + oD, nullptr, v, MROWS, DD, DD);
        scores_kernel<<<dim3(SS / 64, SS / 64, BB * HH), 256>>>(q, k, sc);
        softmax_kernel<<<BB * HH * SS, 256>>>(sc);
        av_kernel<<<dim3(SS / 64, BB * HH), 256>>>(v, sc, av);
        gemm_kernel<<<gD, 256>>>(av, Wo + oDD, bo + oD, h, h, MROWS, DD, DD);

        // --- TreeFFN ---
        ln_kernel<<<MROWS, 256>>>(h, ln2w + oD, ln2b + oD, x);
        gemm_kernel<<<gD, 256>>>(x, Win + oDD, bin_ + oD, nullptr, t, MROWS, DD, DD);
        for (int it = 0; it < 2; it++) {
            gemm_kernel<<<gD, 256>>>(t, Wed + o2,            nullptr, nullptr, t1, MROWS, DD, DD);
            gemm_kernel<<<gD, 256>>>(t, Wed + o2 + DD * DD,  nullptr, nullptr, t2, MROWS, DD, DD);
            combine_kernel<<<ewBlocks, 256>>>(bed + oD);
            gemm_kernel<<<gD, 256>>>(agg, Wg + oDD, bg + oD, nullptr, gl, MROWS, DD, DD);
            gate_kernel<<<ewBlocks, 256>>>();
        }
        add_kernel<<<ewBlocks, 256>>>();
    }

    ln_kernel<<<MROWS, 256>>>(h, lnfw, lnfb, x);
    gemm_kernel<<<gHead, 256>>>(x, Whd, nullptr, nullptr, out, MROWS, VV, DD);
}

// round 2
// speedup vs baseline: 1.4192x; 1.4192x over previous
#include <cuda_runtime.h>
#include <math.h>

// ---------------- problem constants ----------------
#define BB 4
#define SS 1024
#define DD 512
#define HH 8
#define DH 64
#define LL 6
#define VV 32000
#define MROWS (BB*SS)          // 4096
#define EW (BB*SS*DD)          // 2,097,152 elementwise size

// ---------------- device scratch (allocation-free) ----------------
__device__ float g_h[EW];
__device__ float g_x[EW];
__device__ float g_q[EW];
__device__ float g_k[EW];
__device__ float g_v[EW];
__device__ float g_av[EW];
__device__ float g_t[EW];
__device__ float g_t1[EW];
__device__ float g_t2[EW];
__device__ float g_agg[EW];
__device__ float g_gl[EW];
__device__ float g_sc[(size_t)BB*HH*SS*SS];   // 134 MB attention scores

// ---------------- reductions ----------------
__device__ __forceinline__ float warpSum(float v) {
    #pragma unroll
    for (int o = 16; o > 0; o >>= 1) v += __shfl_xor_sync(0xffffffffu, v, o);
    return v;
}
__device__ __forceinline__ float warpMax(float v) {
    #pragma unroll
    for (int o = 16; o > 0; o >>= 1) v = fmaxf(v, __shfl_xor_sync(0xffffffffu, v, o));
    return v;
}
__device__ __forceinline__ float blockSum(float v) {
    __shared__ float sh[8];
    int lane = threadIdx.x & 31, wid = threadIdx.x >> 5;
    v = warpSum(v);
    if (lane == 0) sh[wid] = v;
    __syncthreads();
    if (wid == 0) {
        float x = (lane < 8) ? sh[lane] : 0.f;
        x = warpSum(x);
        if (lane == 0) sh[0] = x;
    }
    __syncthreads();
    float r = sh[0];
    __syncthreads();
    return r;
}
__device__ __forceinline__ float blockMax(float v) {
    __shared__ float sh[8];
    int lane = threadIdx.x & 31, wid = threadIdx.x >> 5;
    v = warpMax(v);
    if (lane == 0) sh[wid] = v;
    __syncthreads();
    if (wid == 0) {
        float x = (lane < 8) ? sh[lane] : -3.0e38f;
        x = warpMax(x);
        if (lane == 0) sh[0] = x;
    }
    __syncthreads();
    float r = sh[0];
    __syncthreads();
    return r;
}

// ---------------- tf32 helpers ----------------
__device__ __forceinline__ float f2tf32(float x) {
    unsigned r;
    asm("cvt.rna.tf32.f32 %0, %1;" : "=r"(r) : "f"(x));
    return __uint_as_float(r);
}
__device__ __forceinline__ void mma_tf32(float* d, const float* a, const float* b) {
    asm volatile(
        "mma.sync.aligned.m16n8k8.row.col.f32.tf32.tf32.f32 "
        "{%0,%1,%2,%3}, {%4,%5,%6,%7}, {%8,%9}, {%0,%1,%2,%3};\n"
        : "+f"(d[0]), "+f"(d[1]), "+f"(d[2]), "+f"(d[3])
        : "r"(__float_as_uint(a[0])), "r"(__float_as_uint(a[1])),
          "r"(__float_as_uint(a[2])), "r"(__float_as_uint(a[3])),
          "r"(__float_as_uint(b[0])), "r"(__float_as_uint(b[1])));
}

// ---------------- embedding ----------------
__global__ void embed_kernel(const int* __restrict__ ids,
                             const float* __restrict__ tok,
                             const float* __restrict__ pos) {
    int idx = blockIdx.x * 256 + threadIdx.x;
    int d  = idx & (DD - 1);
    int bs = idx >> 9;             // DD = 512
    int s  = bs & (SS - 1);
    g_h[idx] = tok[(size_t)ids[bs] * DD + d] + pos[(size_t)s * DD + d];
}

// ---------------- layernorm ----------------
__global__ void ln_kernel(const float* __restrict__ in,
                          const float* __restrict__ w,
                          const float* __restrict__ b,
                          float* __restrict__ out) {
    int row = blockIdx.x;
    const float* xp = in + (size_t)row * DD;
    int t = threadIdx.x;
    float v0 = xp[t];
    float v1 = xp[t + 256];
    float s  = blockSum(v0 + v1);
    float s2 = blockSum(v0 * v0 + v1 * v1);
    float mean = s * (1.f / DD);
    float var  = s2 * (1.f / DD) - mean * mean;
    float rstd = rsqrtf(var + 1e-5f);
    float* op = out + (size_t)row * DD;
    op[t]       = (v0 - mean) * rstd * w[t]       + b[t];
    op[t + 256] = (v1 - mean) * rstd * w[t + 256] + b[t + 256];
}

// ---------------- tensor-core GEMM: C = A@B (+bias) (+add), 3xTF32 ----------------
// A [M,K] row-major, B [K,N] row-major, C [M,N]. M%128==0, N%64==0, K%16==0.
#define TBM 128
#define TBN 64
#define TBK 16
#define APAD 8
#define BPAD 8
__global__ void __launch_bounds__(256)
gemm_tc_kernel(const float* __restrict__ A,
               const float* __restrict__ B,
               const float* __restrict__ bias,
               const float* __restrict__ addv,
               float* __restrict__ C,
               int M, int N, int K) {
    __shared__ float Ah[TBK][TBM + APAD];
    __shared__ float Al[TBK][TBM + APAD];
    __shared__ float Bh[TBK][TBN + BPAD];
    __shared__ float Bl[TBK][TBN + BPAD];

    int bm = blockIdx.y * TBM;
    int bn = blockIdx.x * TBN;
    int tid  = threadIdx.x;
    int lane = tid & 31;
    int warp = tid >> 5;
    int warpM = warp & 3;          // 4 warps along M
    int warpN = warp >> 2;         // 2 warps along N
    int mbase = warpM * 32;
    int nbase = warpN * 32;
    int g  = lane >> 2;            // groupID  (0..7)
    int tg = lane & 3;             // thread in group (0..3)

    float acc[2][4][4];
    #pragma unroll
    for (int i = 0; i < 2; i++)
        #pragma unroll
        for (int j = 0; j < 4; j++)
            #pragma unroll
            for (int c = 0; c < 4; c++) acc[i][j][c] = 0.f;

    for (int k0 = 0; k0 < K; k0 += TBK) {
        // -- fill smem with hi/lo tf32 split --
        #pragma unroll
        for (int i = 0; i < 8; i++) {
            int idx = tid + i * 256;
            int r = idx >> 4, c = idx & 15;          // r: m (0..127), c: k (0..15)
            float v = A[(size_t)(bm + r) * K + k0 + c];
            float hi = f2tf32(v);
            Ah[c][r] = hi;
            Al[c][r] = f2tf32(v - hi);
        }
        #pragma unroll
        for (int i = 0; i < 4; i++) {
            int idx = tid + i * 256;
            int r = idx >> 6, c = idx & 63;          // r: k (0..15), c: n (0..63)
            float v = B[(size_t)(k0 + r) * N + bn + c];
            float hi = f2tf32(v);
            Bh[r][c] = hi;
            Bl[r][c] = f2tf32(v - hi);
        }
        __syncthreads();

        #pragma unroll
        for (int kk = 0; kk < TBK; kk += 8) {
            float ah[2][4], al[2][4];
            #pragma unroll
            for (int mt = 0; mt < 2; mt++) {
                int r0 = mbase + mt * 16 + g;
                ah[mt][0] = Ah[kk + tg][r0];
                ah[mt][1] = Ah[kk + tg][r0 + 8];
                ah[mt][2] = Ah[kk + 4 + tg][r0];
                ah[mt][3] = Ah[kk + 4 + tg][r0 + 8];
                al[mt][0] = Al[kk + tg][r0];
                al[mt][1] = Al[kk + tg][r0 + 8];
                al[mt][2] = Al[kk + 4 + tg][r0];
                al[mt][3] = Al[kk + 4 + tg][r0 + 8];
            }
            float bh[4][2], bl[4][2];
            #pragma unroll
            for (int nt = 0; nt < 4; nt++) {
                int c0 = nbase + nt * 8 + g;
                bh[nt][0] = Bh[kk + tg][c0];
                bh[nt][1] = Bh[kk + 4 + tg][c0];
                bl[nt][0] = Bl[kk + tg][c0];
                bl[nt][1] = Bl[kk + 4 + tg][c0];
            }
            #pragma unroll
            for (int mt = 0; mt < 2; mt++)
                #pragma unroll
                for (int nt = 0; nt < 4; nt++) {
                    mma_tf32(acc[mt][nt], ah[mt], bh[nt]);   // hi*hi
                    mma_tf32(acc[mt][nt], ah[mt], bl[nt]);   // hi*lo
                    mma_tf32(acc[mt][nt], al[mt], bh[nt]);   // lo*hi
                }
        }
        __syncthreads();
    }

    // -- epilogue --
    #pragma unroll
    for (int mt = 0; mt < 2; mt++) {
        #pragma unroll
        for (int nt = 0; nt < 4; nt++) {
            int row0 = bm + mbase + mt * 16 + g;
            int col0 = bn + nbase + nt * 8 + 2 * tg;
            #pragma unroll
            for (int half = 0; half < 2; half++) {
                size_t r = row0 + half * 8;
                float v0 = acc[mt][nt][half * 2 + 0];
                float v1 = acc[mt][nt][half * 2 + 1];
                if (bias) { v0 += bias[col0]; v1 += bias[col0 + 1]; }
                if (addv) { v0 += addv[r * N + col0]; v1 += addv[r * N + col0 + 1]; }
                C[r * N + col0]     = v0;
                C[r * N + col0 + 1] = v1;
            }
        }
    }
}

// ---------------- attention: scores tile (skips masked tiles) ----------------
__global__ void scores_kernel(const float* __restrict__ q,
                              const float* __restrict__ k,
                              float* __restrict__ sc) {
    int tj = blockIdx.x, ti = blockIdx.y;
    if (tj > ti) return;
    int bh = blockIdx.z;
    int b = bh >> 3, h = bh & 7;
    __shared__ float Qs[64][65];
    __shared__ float Ks[64][65];
    int tid = threadIdx.x;
    const float* qb = q + (size_t)(b * SS + ti * 64) * DD + h * DH;
    const float* kb = k + (size_t)(b * SS + tj * 64) * DD + h * DH;
    #pragma unroll
    for (int t = 0; t < 16; t++) {
        int idx = tid + t * 256;
        int r = idx >> 6, d = idx & 63;
        Qs[d][r] = qb[(size_t)r * DD + d];
        Ks[d][r] = kb[(size_t)r * DD + d];
    }
    __syncthreads();
    int tx = tid & 15, ty = tid >> 4;
    float acc[4][4] = {};
    #pragma unroll 16
    for (int d = 0; d < 64; d++) {
        float qa[4], ka[4];
        #pragma unroll
        for (int i = 0; i < 4; i++) qa[i] = Qs[d][ty * 4 + i];
        #pragma unroll
        for (int j = 0; j < 4; j++) ka[j] = Ks[d][tx * 4 + j];
        #pragma unroll
        for (int i = 0; i < 4; i++)
            #pragma unroll
            for (int j = 0; j < 4; j++)
                acc[i][j] = fmaf(qa[i], ka[j], acc[i][j]);
    }
    float* srow = sc + (size_t)bh * SS * SS;
    #pragma unroll
    for (int i = 0; i < 4; i++) {
        int gi = ti * 64 + ty * 4 + i;
        #pragma unroll
        for (int j = 0; j < 4; j++) {
            int gj = tj * 64 + tx * 4 + j;
            float val = acc[i][j] * 0.125f;   // 1/sqrt(64)
            if (gj > gi) val = -1e30f;
            srow[(size_t)gi * SS + gj] = val;
        }
    }
}

// ---------------- softmax over valid prefix (rounded up to tile) ----------------
__global__ void softmax_kernel(float* __restrict__ sc) {
    int row = blockIdx.x;                 // = bh*SS + i
    int i = row & (SS - 1);
    float* p = sc + (size_t)row * SS;
    int n = ((i >> 6) + 1) << 6;          // columns AV will read
    int tid = threadIdx.x;
    float vals[4];
    int cnt = 0;
    for (int j = tid; j < n; j += 256) vals[cnt++] = p[j];
    float m = -1e30f;
    for (int c = 0; c < cnt; c++) m = fmaxf(m, vals[c]);
    m = blockMax(m);
    float e[4], s = 0.f;
    for (int c = 0; c < cnt; c++) { e[c] = expf(vals[c] - m); s += e[c]; }
    s = blockSum(s);
    float inv = 1.f / s;
    cnt = 0;
    for (int j = tid; j < n; j += 256) p[j] = e[cnt++] * inv;
}

// ---------------- AV: attn @ v, K-loop truncated at diagonal ----------------
__global__ void av_kernel(const float* __restrict__ v,
                          const float* __restrict__ sc,
                          float* __restrict__ av) {
    int ti = blockIdx.x;
    int bh = blockIdx.y;
    int b = bh >> 3, h = bh & 7;
    __shared__ float Ps[64][33];
    __shared__ float Vs[32][64];
    const float* srow = sc + (size_t)bh * SS * SS + (size_t)ti * 64 * SS;
    const float* vb = v + (size_t)b * SS * DD + h * DH;
    int tid = threadIdx.x, tx = tid & 15, ty = tid >> 4;
    float acc[4][4] = {};
    int kmax = (ti + 1) * 64;
    for (int k0 = 0; k0 < kmax; k0 += 32) {
        #pragma unroll
        for (int t = 0; t < 8; t++) {
            int idx = tid + t * 256;
            int r = idx >> 5, c = idx & 31;
            Ps[r][c] = srow[(size_t)r * SS + k0 + c];
        }
        #pragma unroll
        for (int t = 0; t < 8; t++) {
            int idx = tid + t * 256;
            int r = idx >> 6, c = idx & 63;
            Vs[r][c] = vb[(size_t)(k0 + r) * DD + c];
        }
        __syncthreads();
        #pragma unroll
        for (int kk = 0; kk < 32; kk++) {
            float a[4], bv[4];
            #pragma unroll
            for (int i = 0; i < 4; i++) a[i] = Ps[ty * 4 + i][kk];
            #pragma unroll
            for (int j = 0; j < 4; j++) bv[j] = Vs[kk][tx * 4 + j];
            #pragma unroll
            for (int i = 0; i < 4; i++)
                #pragma unroll
                for (int j = 0; j < 4; j++)
                    acc[i][j] = fmaf(a[i], bv[j], acc[i][j]);
        }
        __syncthreads();
    }
    float* ob = av + (size_t)(b * SS + ti * 64) * DD + h * DH;
    #pragma unroll
    for (int i = 0; i < 4; i++)
        #pragma unroll
        for (int j = 0; j < 4; j++)
            ob[(size_t)(ty * 4 + i) * DD + tx * 4 + j] = acc[i][j];
}

// ---------------- TreeFFN elementwise ----------------
__global__ void combine_kernel(const float* __restrict__ bedge) {
    int idx = blockIdx.x * 256 + threadIdx.x;
    int d = idx & (DD - 1);
    int s = (idx >> 9) & (SS - 1);
    float r = 0.f;
    if (s != 0) {
        float m = g_t1[idx - DD] + g_t2[idx] + bedge[d];
        r = m > 0.f ? m : 0.f;
    }
    g_agg[idx] = r;
}
__global__ void gate_kernel() {
    int idx = blockIdx.x * 256 + threadIdx.x;
    float g = 1.f / (1.f + expf(-g_gl[idx]));
    g_t[idx] += g * g_agg[idx];
}
__global__ void add_kernel() {
    int idx = blockIdx.x * 256 + threadIdx.x;
    g_h[idx] += g_t[idx];
}

// ---------------- launcher ----------------
extern "C" void kernel_launch(void* const* d_in, const int* in_sizes, int n_in,
                              void* d_out, int out_size) {
    const int*   ids  = (const int*)  d_in[0];
    const float* tok  = (const float*)d_in[1];
    const float* pos  = (const float*)d_in[2];
    const float* Wq   = (const float*)d_in[3];
    const float* bq   = (const float*)d_in[4];
    const float* Wk   = (const float*)d_in[5];
    const float* bk   = (const float*)d_in[6];
    const float* Wv   = (const float*)d_in[7];
    const float* bv   = (const float*)d_in[8];
    const float* Wo   = (const float*)d_in[9];
    const float* bo   = (const float*)d_in[10];
    const float* ln1w = (const float*)d_in[11];
    const float* ln1b = (const float*)d_in[12];
    const float* ln2w = (const float*)d_in[13];
    const float* ln2b = (const float*)d_in[14];
    const float* Win  = (const float*)d_in[15];
    const float* bin_ = (const float*)d_in[16];
    const float* Wed  = (const float*)d_in[17];
    const float* bed  = (const float*)d_in[18];
    const float* Wg   = (const float*)d_in[19];
    const float* bg   = (const float*)d_in[20];
    const float* lnfw = (const float*)d_in[21];
    const float* lnfb = (const float*)d_in[22];
    const float* Whd  = (const float*)d_in[23];
    float* out = (float*)d_out;

    float *h, *x, *q, *k, *v, *av, *t, *t1, *t2, *agg, *gl, *sc;
    cudaGetSymbolAddress((void**)&h,   g_h);
    cudaGetSymbolAddress((void**)&x,   g_x);
    cudaGetSymbolAddress((void**)&q,   g_q);
    cudaGetSymbolAddress((void**)&k,   g_k);
    cudaGetSymbolAddress((void**)&v,   g_v);
    cudaGetSymbolAddress((void**)&av,  g_av);
    cudaGetSymbolAddress((void**)&t,   g_t);
    cudaGetSymbolAddress((void**)&t1,  g_t1);
    cudaGetSymbolAddress((void**)&t2,  g_t2);
    cudaGetSymbolAddress((void**)&agg, g_agg);
    cudaGetSymbolAddress((void**)&gl,  g_gl);
    cudaGetSymbolAddress((void**)&sc,  g_sc);

    const int ewBlocks = EW / 256;         // 8192
    dim3 gD(DD / TBN, MROWS / TBM);        // (8, 32)  N=512 GEMMs
    dim3 gHead(VV / TBN, MROWS / TBM);     // (500, 32)

    embed_kernel<<<ewBlocks, 256>>>(ids, tok, pos);

    for (int l = 0; l < LL; l++) {
        size_t oDD = (size_t)l * DD * DD;
        size_t oD  = (size_t)l * DD;
        size_t o2  = (size_t)l * 2 * DD * DD;

        // --- attention ---
        ln_kernel<<<MROWS, 256>>>(h, ln1w + oD, ln1b + oD, x);
        gemm_tc_kernel<<<gD, 256>>>(x, Wq + oDD, bq + oD, nullptr, q, MROWS, DD, DD);
        gemm_tc_kernel<<<gD, 256>>>(x, Wk + oDD, bk + oD, nullptr, k, MROWS, DD, DD);
        gemm_tc_kernel<<<gD, 256>>>(x, Wv + oDD, bv + oD, nullptr, v, MROWS, DD, DD);
        scores_kernel<<<dim3(SS / 64, SS / 64, BB * HH), 256>>>(q, k, sc);
        softmax_kernel<<<BB * HH * SS, 256>>>(sc);
        av_kernel<<<dim3(SS / 64, BB * HH), 256>>>(v, sc, av);
        gemm_tc_kernel<<<gD, 256>>>(av, Wo + oDD, bo + oD, h, h, MROWS, DD, DD);

        // --- TreeFFN ---
        ln_kernel<<<MROWS, 256>>>(h, ln2w + oD, ln2b + oD, x);
        gemm_tc_kernel<<<gD, 256>>>(x, Win + oDD, bin_ + oD, nullptr, t, MROWS, DD, DD);
        for (int it = 0; it < 2; it++) {
            gemm_tc_kernel<<<gD, 256>>>(t, Wed + o2,           nullptr, nullptr, t1, MROWS, DD, DD);
            gemm_tc_kernel<<<gD, 256>>>(t, Wed + o2 + DD * DD, nullptr, nullptr, t2, MROWS, DD, DD);
            combine_kernel<<<ewBlocks, 256>>>(bed + oD);
            gemm_tc_kernel<<<gD, 256>>>(agg, Wg + oDD, bg + oD, nullptr, gl, MROWS, DD, DD);
            gate_kernel<<<ewBlocks, 256>>>();
        }
        add_kernel<<<ewBlocks, 256>>>();
    }

    ln_kernel<<<MROWS, 256>>>(h, lnfw, lnfb, x);
    gemm_tc_kernel<<<gHead, 256>>>(x, Whd, nullptr, nullptr, out, MROWS, VV, DD);
}